// round 12
// baseline (speedup 1.0000x reference)
#include <cuda_runtime.h>
#include <cuda_bf16.h>

// Fixed shapes: B=4, L=2048
#define BQ 4
#define LQ 2048
#define MSEG (LQ - 1)              // 2047 segments per path

#define THREADS 256
#define NSET 4                      // packed f32x2 sets per thread
#define UI (2 * NSET)               // 8 i-segments per thread
#define IPB (THREADS * UI)          // 2048 >= 2047  -> IT = 1
#define JT 74
#define JPB 28                      // 74*28 = 2072 >= 2047
#define NBLOCKS (BQ * JT)           // 296 = 148 SMs * 2 CTAs (one balanced wave)
#define PER_B JT                    // 74 partials per batch

typedef unsigned long long u64;

// Scratch (no cudaMalloc allowed)
__device__ float        g_partial[NBLOCKS];
__device__ unsigned int g_count = 0;

// ---- packed f32x2 helpers (sm_100+ PTX) ----
__device__ __forceinline__ u64 pk2(float lo, float hi) {
    u64 r; asm("mov.b64 %0, {%1, %2};" : "=l"(r) : "f"(lo), "f"(hi)); return r;
}
__device__ __forceinline__ void upk2(u64 v, float& lo, float& hi) {
    asm("mov.b64 {%0, %1}, %2;" : "=f"(lo), "=f"(hi) : "l"(v));
}
__device__ __forceinline__ u64 f2fma(u64 a, u64 b, u64 c) {
    u64 d; asm("fma.rn.f32x2 %0, %1, %2, %3;" : "=l"(d) : "l"(a), "l"(b), "l"(c)); return d;
}
__device__ __forceinline__ u64 f2add(u64 a, u64 b) {
    u64 d; asm("add.rn.f32x2 %0, %1, %2;" : "=l"(d) : "l"(a), "l"(b)); return d;
}
__device__ __forceinline__ u64 f2mul(u64 a, u64 b) {
    u64 d; asm("mul.rn.f32x2 %0, %1, %2;" : "=l"(d) : "l"(a), "l"(b)); return d;
}
__device__ __forceinline__ float frsq(float x) {
    float r; asm("rsqrt.approx.f32 %0, %1;" : "=f"(r) : "f"(x)); return r;
}

__device__ __forceinline__ float3 norm_imag4(float4 q) {
    float s  = q.x * q.x + q.y * q.y + q.z * q.z + q.w * q.w;
    float rs = rsqrtf(fmaxf(s, 1e-30f));
    float nrm = s * rs;                          // |q|
    float inv = __fdividef(1.0f, nrm + 1e-12f);
    return make_float3(q.y * inv, q.z * inv, q.w * inv);
}

__global__ __launch_bounds__(THREADS, 2)
void gauss_linking_fused(const float* __restrict__ qa,
                         const float* __restrict__ qb,
                         float* __restrict__ out) {
    __shared__ float  pA[(IPB + 1) * 3];                 // 24.6 KB
    __shared__ float  pB[(JPB + 1) * 3];
    // per-j packed duplicated operands: {-rbx,-rby,-rbz, dbx,dby,dbz, gx,gy,gz, pad}
    __shared__ __align__(16) u64 sj[JPB * 10];           // 2.2 KB
    __shared__ float  red[THREADS];
    __shared__ double sdd[BQ];
    __shared__ int    lastFlag;

    const int b  = blockIdx.z;
    const int jt = blockIdx.x;
    const int t  = threadIdx.x;

    // ---- Stage & normalize full A-point range (IT = 1) ----
    const int segcnt = MSEG;                             // 2047
    for (int p = t; p < MSEG + 1; p += THREADS) {
        float4 q = *reinterpret_cast<const float4*>(qa + ((long)(b * LQ + p)) * 4);
        float3 v = norm_imag4(q);
        pA[p * 3 + 0] = v.x; pA[p * 3 + 1] = v.y; pA[p * 3 + 2] = v.z;
    }

    // ---- Stage & normalize B-point tile, build duplicated per-j data ----
    const int j0     = jt * JPB;
    const int jcount = min(JPB, MSEG - j0);              // 28 (3 for last tile)
    if (t <= jcount) {
        float4 q = *reinterpret_cast<const float4*>(qb + ((long)(b * LQ + j0 + t)) * 4);
        float3 v = norm_imag4(q);
        pB[t * 3 + 0] = v.x; pB[t * 3 + 1] = v.y; pB[t * 3 + 2] = v.z;
    }
    __syncthreads();
    if (t < jcount) {
        float x0 = pB[t * 3 + 0], y0 = pB[t * 3 + 1], z0 = pB[t * 3 + 2];
        float x1 = pB[t * 3 + 3], y1 = pB[t * 3 + 4], z1 = pB[t * 3 + 5];
        float rbx = (x1 + x0) * 0.5f, rby = (y1 + y0) * 0.5f, rbz = (z1 + z0) * 0.5f;
        float dbx = x1 - x0,          dby = y1 - y0,          dbz = z1 - z0;
        float gx = rby * dbz - rbz * dby;                 // g = rb x db
        float gy = rbz * dbx - rbx * dbz;
        float gz = rbx * dby - rby * dbx;
        u64* s = sj + t * 10;
        s[0] = pk2(-rbx, -rbx);  s[1] = pk2(-rby, -rby);  s[2] = pk2(-rbz, -rbz);
        s[3] = pk2(dbx, dbx);    s[4] = pk2(dby, dby);    s[5] = pk2(dbz, dbz);
        s[6] = pk2(gx, gx);      s[7] = pk2(gy, gy);      s[8] = pk2(gz, gz);
    }
    __syncthreads();

    // ---- Register-resident i-segments, packed: set s holds (u=2s lo, u=2s+1 hi) ----
    u64 axp[NSET], ayp[NSET], azp[NSET];
    u64 daxp[NSET], dayp[NSET], dazp[NSET];
    u64 haxp[NSET], hayp[NSET], hazp[NSET];
    #pragma unroll
    for (int s = 0; s < NSET; s++) {
        float ax[2], ay[2], az[2], dx[2], dy[2], dz[2], hx[2], hy[2], hz[2];
        #pragma unroll
        for (int h = 0; h < 2; h++) {
            int i = (2 * s + h) * THREADS + t;
            if (i < segcnt) {
                float x0 = pA[i * 3 + 0], y0 = pA[i * 3 + 1], z0 = pA[i * 3 + 2];
                float x1 = pA[i * 3 + 3], y1 = pA[i * 3 + 4], z1 = pA[i * 3 + 5];
                ax[h] = (x1 + x0) * 0.5f; ay[h] = (y1 + y0) * 0.5f; az[h] = (z1 + z0) * 0.5f;
                dx[h] = x1 - x0;          dy[h] = y1 - y0;          dz[h] = z1 - z0;
                hx[h] = ay[h] * dz[h] - az[h] * dy[h];    // ha = ra x da
                hy[h] = az[h] * dx[h] - ax[h] * dz[h];
                hz[h] = ax[h] * dy[h] - ay[h] * dx[h];
            } else {
                ax[h] = ay[h] = az[h] = 0.f;
                dx[h] = dy[h] = dz[h] = 0.f;
                hx[h] = hy[h] = hz[h] = 0.f;              // num = 0 -> contributes 0
            }
        }
        axp[s]  = pk2(ax[0], ax[1]);  ayp[s]  = pk2(ay[0], ay[1]);  azp[s]  = pk2(az[0], az[1]);
        daxp[s] = pk2(dx[0], dx[1]);  dayp[s] = pk2(dy[0], dy[1]);  dazp[s] = pk2(dz[0], dz[1]);
        haxp[s] = pk2(hx[0], hx[1]);  hayp[s] = pk2(hy[0], hy[1]);  hazp[s] = pk2(hz[0], hz[1]);
    }
    const u64 NEG3EPS = pk2(-3e-6f, -3e-6f);
    const u64 ONE2    = pk2(1.0f, 1.0f);
    const u64 TINY2   = pk2(1e-24f, 1e-24f);

    // ---- Main all-pairs loop: 4 independent packed chains per thread ----
    // num = rd.(da x db) = (ra x da).db + da.(rb x db) = ha.db + da.g
    // 1/(|r|+eps)^3 = rs^3 * (1+eps*rs)^-3 ~= rs^3 * (1 - 3*eps*rs)
    u64 acc2[2] = {0ull, 0ull};     // sets 0,1 -> acc2[0]; sets 2,3 -> acc2[1]
    #pragma unroll 1
    for (int j = 0; j < jcount; j++) {
        const u64* sp = sj + j * 10;
        const ulonglong2 p01 = *reinterpret_cast<const ulonglong2*>(sp);      // -rbx -rby
        const ulonglong2 p23 = *reinterpret_cast<const ulonglong2*>(sp + 2);  // -rbz  dbx
        const ulonglong2 p45 = *reinterpret_cast<const ulonglong2*>(sp + 4);  //  dby  dbz
        const ulonglong2 p67 = *reinterpret_cast<const ulonglong2*>(sp + 6);  //  gx   gy
        const u64 gz2 = sp[8];

        // Phase 1: d2 for all sets (independent chains)
        u64 d2[NSET];
        #pragma unroll
        for (int s = 0; s < NSET; s++) {
            u64 rdx = f2add(axp[s], p01.x);
            u64 rdy = f2add(ayp[s], p01.y);
            u64 rdz = f2add(azp[s], p23.x);
            u64 d   = f2fma(rdx, rdx, TINY2);
            d       = f2fma(rdy, rdy, d);
            d2[s]   = f2fma(rdz, rdz, d);
        }
        // Phase 2: issue all MUFUs
        u64 rs[NSET];
        #pragma unroll
        for (int s = 0; s < NSET; s++) {
            float d0, d1;
            upk2(d2[s], d0, d1);
            rs[s] = pk2(frsq(d0), frsq(d1));
        }
        // Phase 3: numerators (independent of MUFU results -> hides latency)
        u64 num[NSET];
        #pragma unroll
        for (int s = 0; s < NSET; s++) {
            u64 n = f2fma(hazp[s], p45.y, f2fma(hayp[s], p45.x, f2mul(haxp[s], p23.y)));
            num[s] = f2fma(dazp[s], gz2, f2fma(dayp[s], p67.y, f2fma(daxp[s], p67.x, n)));
        }
        // Phase 4: epilogue
        #pragma unroll
        for (int s = 0; s < NSET; s++) {
            u64 rs3 = f2mul(f2mul(rs[s], rs[s]), rs[s]);
            u64 fac = f2fma(rs[s], NEG3EPS, ONE2);
            acc2[s >> 1] = f2fma(f2mul(num[s], rs3), fac, acc2[s >> 1]);
        }
    }

    float l0, h0, l1, h1;
    upk2(acc2[0], l0, h0);
    upk2(acc2[1], l1, h1);
    float acc = (l0 + h0) + (l1 + h1);

    // ---- Deterministic block tree-reduce ----
    red[t] = acc;
    __syncthreads();
    #pragma unroll
    for (int off = THREADS / 2; off >= 1; off >>= 1) {
        if (t < off) red[t] += red[t + off];
        __syncthreads();
    }

    // ---- Last-block-done final reduction (deterministic fixed order) ----
    if (t == 0) {
        g_partial[b * PER_B + jt] = red[0];
        __threadfence();
        unsigned int tk = atomicAdd(&g_count, 1u);
        lastFlag = (tk == NBLOCKS - 1u) ? 1 : 0;
    }
    __syncthreads();

    if (lastFlag) {
        int w = t >> 5, l = t & 31;
        if (w < BQ) {
            double s = 0.0;
            for (int k = l; k < PER_B; k += 32)
                s += (double)__ldcg(&g_partial[w * PER_B + k]);
            #pragma unroll
            for (int off = 16; off >= 1; off >>= 1)
                s += __shfl_down_sync(0xffffffffu, s, off);
            if (l == 0) sdd[w] = fabs(s);
        }
        __syncthreads();
        if (t == 0) {
            double tot = sdd[0] + sdd[1] + sdd[2] + sdd[3];
            out[0] = (float)(tot / ((double)BQ * 4.0 * 3.14159265358979323846));
            g_count = 0;   // reset for next graph replay
        }
    }
}

extern "C" void kernel_launch(void* const* d_in, const int* in_sizes, int n_in,
                              void* d_out, int out_size) {
    const float* qa = (const float*)d_in[0];   // genomic_quats [B,L,4]
    const float* qb = (const float*)d_in[1];   // code_quats    [B,L,4]
    float* out = (float*)d_out;

    dim3 grid(JT, 1, BQ);                      // 296 blocks
    gauss_linking_fused<<<grid, THREADS>>>(qa, qb, out);
}